// round 15
// baseline (speedup 1.0000x reference)
#include <cuda_runtime.h>
#include <cuda_bf16.h>
#include <cstring>
#include <cstdint>

// ---------------------------------------------------------------------------
// HyperEConv, HMMA bf16-split GEMMs. Self-cleaning CSR, vectorized edge passes.
//   hist/place: 2 edges per thread (int2 loads), atomics at L2 floor
//   offsets reads cnt -> beg/cur, then zeros cnt (restores invariant)
//   place fills src lists, cur becomes segment END; thread0 zeros counters
//   seg_reduce/final use (beg, end=cur); deg = end-beg
// Streams: A: conv_w, xv ; B: hist, offsets, place ; C: wv, we ; 0: sr1,sr2,final
// GEMM: D = Ahi*Bhi + Ahi*Blo + Alo*Bhi  (bf16 in, fp32 accum)
// Output: [w_new (N_W*128) | x_new (N_X*128)]  float32
// ---------------------------------------------------------------------------

#define MAX_NX 100000
#define MAX_NW 25000
#define MAX_E  800000
#define D 128

__device__ float g_xv [MAX_NX * D];
__device__ float g_wv [MAX_NW * D];
__device__ float g_we [MAX_NW * D];
__device__ float g_s  [MAX_NW * D];

// precomputed bf16 weights: [mat][hi=0/lo=1][2048 uint4] swizzled
__device__ uint4 g_wbf[4][2][2048];

// counts: x segs [0,NX), w segs [NX,NX+NW), 2 counters after that.
// INVARIANT: region [0, NX+NW+2) all-zero at entry of every run
// (static zero-init first run; offsets zeros cnt, place zeros counters).
__device__ int g_cnt [MAX_NX + MAX_NW + 2];
__device__ int g_beg [MAX_NX + MAX_NW];
__device__ int g_cur [MAX_NX + MAX_NW];   // after place: segment END offsets
__device__ int g_srcx[MAX_E];
__device__ int g_srcw[MAX_E];

__device__ __forceinline__ uint32_t smem_u32(const void* p) {
    uint32_t a;
    asm("{ .reg .u64 t; cvta.to.shared.u64 t, %1; cvt.u32.u64 %0, t; }"
        : "=r"(a) : "l"(p));
    return a;
}

__device__ __forceinline__ void ldmx4(uint32_t* r, uint32_t addr) {
    asm volatile("ldmatrix.sync.aligned.m8n8.x4.shared.b16 {%0,%1,%2,%3}, [%4];"
                 : "=r"(r[0]), "=r"(r[1]), "=r"(r[2]), "=r"(r[3]) : "r"(addr));
}

__device__ __forceinline__ void mma_bf16(float* d, const uint32_t* a,
                                         uint32_t b0, uint32_t b1) {
    asm volatile(
        "mma.sync.aligned.m16n8k16.row.col.f32.bf16.bf16.f32 "
        "{%0,%1,%2,%3}, {%4,%5,%6,%7}, {%8,%9}, {%0,%1,%2,%3};"
        : "+f"(d[0]), "+f"(d[1]), "+f"(d[2]), "+f"(d[3])
        : "r"(a[0]), "r"(a[1]), "r"(a[2]), "r"(a[3]), "r"(b0), "r"(b1));
}

__device__ __forceinline__ void split2(float f0, float f1, uint32_t& hi, uint32_t& lo) {
    __nv_bfloat162 hh = __floats2bfloat162_rn(f0, f1);
    float r0 = f0 - __bfloat162float(hh.x);
    float r1 = f1 - __bfloat162float(hh.y);
    __nv_bfloat162 ll = __floats2bfloat162_rn(r0, r1);
    memcpy(&hi, &hh, 4);
    memcpy(&lo, &ll, 4);
}

#define SM_AHI  0
#define SM_ALO  16384
#define SM_BHI  32768
#define SM_BLO  65536
#define SM_TOT  98304

extern __shared__ char smc[];

// ---------------------------------------------------------------------------
// Weight precompute: 4 [128x128] fp32 -> swizzled bf16 hi/lo
// ---------------------------------------------------------------------------
__global__ void conv_w_kernel(const float* __restrict__ W0, const float* __restrict__ W1,
                              const float* __restrict__ W2, const float* __restrict__ W3)
{
    const int t = blockIdx.x * blockDim.x + threadIdx.x;
    if (t >= 8192) return;
    const int mat = t >> 11;
    const int rem = t & 2047;
    const int r = rem >> 4;
    const int c = rem & 15;
    const float* Wm = (mat == 0) ? W0 : (mat == 1) ? W1 : (mat == 2) ? W2 : W3;
    const float4 u = *(const float4*)(Wm + r * 128 + c * 8);
    const float4 v = *(const float4*)(Wm + r * 128 + c * 8 + 4);
    uint4 hi, lo;
    split2(u.x, u.y, hi.x, lo.x);
    split2(u.z, u.w, hi.y, lo.y);
    split2(v.x, v.y, hi.z, lo.z);
    split2(v.z, v.w, hi.w, lo.w);
    const int off = r * 16 + (c ^ (r & 7));
    g_wbf[mat][0][off] = hi;
    g_wbf[mat][1][off] = lo;
}

__device__ __forceinline__ void load_weights_smem(int wmat, int tid) {
    const uint4* whi = g_wbf[wmat][0];
    const uint4* wlo = g_wbf[wmat][1];
    uint4* shi = (uint4*)(smc + SM_BHI);
    uint4* slo = (uint4*)(smc + SM_BLO);
    #pragma unroll
    for (int it = 0; it < 8; it++) {
        const int i = tid + it * 256;
        shi[i] = whi[i];
        slo[i] = wlo[i];
    }
}

__device__ __forceinline__ void mma_mainloop(uint32_t sb, int tid, float acc[2][4][4]) {
    const int lane = tid & 31;
    const int wid  = tid >> 5;
    const int m0 = (wid & 1) * 32;
    const int n0 = (wid >> 1) * 32;
    const int sub = lane >> 3, l8 = lane & 7;
    for (int ks = 0; ks < 8; ks++) {
        uint32_t ahi[2][4], alo[2][4], bhi[2][4], blo[2][4];
        #pragma unroll
        for (int at = 0; at < 2; at++) {
            const int ar  = m0 + at * 16 + (sub & 1) * 8 + l8;
            const int akc = ks * 2 + (sub >> 1);
            const uint32_t aoff = (uint32_t)ar * 256u + (uint32_t)((akc ^ (ar & 7)) << 4);
            ldmx4(ahi[at], sb + SM_AHI + aoff);
            ldmx4(alo[at], sb + SM_ALO + aoff);
        }
        #pragma unroll
        for (int bp = 0; bp < 2; bp++) {
            const int br  = n0 + bp * 16 + (sub >> 1) * 8 + l8;
            const int bkc = ks * 2 + (sub & 1);
            const uint32_t boff = (uint32_t)br * 256u + (uint32_t)((bkc ^ (br & 7)) << 4);
            ldmx4(bhi[bp], sb + SM_BHI + boff);
            ldmx4(blo[bp], sb + SM_BLO + boff);
        }
        #pragma unroll
        for (int at = 0; at < 2; at++) {
            #pragma unroll
            for (int nt = 0; nt < 4; nt++) {
                const int bp = nt >> 1, o = (nt & 1) * 2;
                mma_bf16(acc[at][nt], ahi[at], bhi[bp][o], bhi[bp][o + 1]);
                mma_bf16(acc[at][nt], ahi[at], blo[bp][o], blo[bp][o + 1]);
                mma_bf16(acc[at][nt], alo[at], bhi[bp][o], bhi[bp][o + 1]);
            }
        }
    }
}

// ---------------------------------------------------------------------------
// HMMA GEMM: v = A@W^T + bias*deg ; deg = degE[r]-degB[r] (1 if degB null)
//   out = mul ? mul*(1+v) : v
// ---------------------------------------------------------------------------
__global__ void __launch_bounds__(256, 2)
gemm_hmma_kernel(const float* __restrict__ A, int wmat,
                 const float* __restrict__ bias, float* __restrict__ C, int M,
                 const int* __restrict__ degB, const int* __restrict__ degE,
                 const float* __restrict__ mulSrc)
{
    const uint32_t sb = smem_u32(smc);
    const int tid = threadIdx.x;
    const int lane = tid & 31;
    const int wid  = tid >> 5;
    const int rowBase = blockIdx.x * 64;

    load_weights_smem(wmat, tid);

    #pragma unroll
    for (int it = 0; it < 4; it++) {
        const int task = tid + it * 256;
        const int r = task >> 4;
        const int c = task & 15;
        const int grow = rowBase + r;
        float4 u = make_float4(0.f, 0.f, 0.f, 0.f), v = u;
        if (grow < M) {
            const float* Ar = A + (size_t)grow * D + c * 8;
            u = *(const float4*)Ar;
            v = *(const float4*)(Ar + 4);
        }
        uint4 hi, lo;
        split2(u.x, u.y, hi.x, lo.x);
        split2(u.z, u.w, hi.y, lo.y);
        split2(v.x, v.y, hi.z, lo.z);
        split2(v.z, v.w, hi.w, lo.w);
        const uint32_t off = (uint32_t)r * 256u + (uint32_t)((c ^ (r & 7)) << 4);
        *(uint4*)(smc + SM_AHI + off) = hi;
        *(uint4*)(smc + SM_ALO + off) = lo;
    }
    __syncthreads();

    float acc[2][4][4];
    #pragma unroll
    for (int at = 0; at < 2; at++)
        #pragma unroll
        for (int nt = 0; nt < 4; nt++)
            #pragma unroll
            for (int q = 0; q < 4; q++) acc[at][nt][q] = 0.f;

    mma_mainloop(sb, tid, acc);

    const int m0 = (wid & 1) * 32;
    const int n0 = (wid >> 1) * 32;
    const bool hasMul = (mulSrc != nullptr);
    #pragma unroll
    for (int at = 0; at < 2; at++) {
        const int rA = rowBase + m0 + at * 16 + (lane >> 2);
        const int rB = rA + 8;
        float dA = 1.f, dB = 1.f;
        if (degB != nullptr) {
            if (rA < M) dA = (float)(degE[rA] - degB[rA]);
            if (rB < M) dB = (float)(degE[rB] - degB[rB]);
        }
        #pragma unroll
        for (int nt = 0; nt < 4; nt++) {
            const int col = n0 + nt * 8 + (lane & 3) * 2;
            const float2 b2 = *(const float2*)(bias + col);
            if (rA < M) {
                float v0 = acc[at][nt][0] + b2.x * dA;
                float v1 = acc[at][nt][1] + b2.y * dA;
                if (hasMul) {
                    float2 m = *(const float2*)(mulSrc + (size_t)rA * D + col);
                    v0 = fmaf(m.x, v0, m.x);
                    v1 = fmaf(m.y, v1, m.y);
                }
                *(float2*)(C + (size_t)rA * D + col) = make_float2(v0, v1);
            }
            if (rB < M) {
                float v0 = acc[at][nt][2] + b2.x * dB;
                float v1 = acc[at][nt][3] + b2.y * dB;
                if (hasMul) {
                    float2 m = *(const float2*)(mulSrc + (size_t)rB * D + col);
                    v0 = fmaf(m.x, v0, m.x);
                    v1 = fmaf(m.y, v1, m.y);
                }
                *(float2*)(C + (size_t)rB * D + col) = make_float2(v0, v1);
            }
        }
    }
}

// ---------------------------------------------------------------------------
// CSR build, 2 edges per thread (int2 loads). Self-cleaning.
// ---------------------------------------------------------------------------
__global__ void hist_kernel(const int* __restrict__ vidx, const int* __restrict__ eidx,
                            int* __restrict__ cnt, int nx, int E)
{
    const int t = blockIdx.x * blockDim.x + threadIdx.x;
    const int e = t * 2;
    if (e + 1 < E) {
        int2 v2 = *(const int2*)(vidx + e);
        int2 h2 = *(const int2*)(eidx + e);
        atomicAdd(&cnt[v2.x], 1);
        atomicAdd(&cnt[v2.y], 1);
        atomicAdd(&cnt[nx + h2.x], 1);
        atomicAdd(&cnt[nx + h2.y], 1);
    } else if (e < E) {
        atomicAdd(&cnt[vidx[e]], 1);
        atomicAdd(&cnt[nx + eidx[e]], 1);
    }
}

// per-block scan + atomic base grab; zeros cnt after reading (invariant restore)
__global__ void __launch_bounds__(1024)
offsets_kernel(int* __restrict__ cnt, int* __restrict__ beg,
               int* __restrict__ cur, int* __restrict__ ctr,
               int nx, int nw, int nbx)
{
    const int isW = (blockIdx.x >= nbx) ? 1 : 0;
    const int blk = isW ? (blockIdx.x - nbx) : blockIdx.x;
    const int n   = isW ? nw : nx;
    const int off = isW ? nx : 0;

    const int t = threadIdx.x;
    const int i = blk * 1024 + t;
    int v = (i < n) ? cnt[off + i] : 0;

    const int lane = t & 31, wd = t >> 5;
    int s = v;
    #pragma unroll
    for (int o = 1; o < 32; o <<= 1) {
        int u = __shfl_up_sync(0xffffffffu, s, o);
        if (lane >= o) s += u;
    }
    __shared__ int wsum[32];
    __shared__ int base;
    if (lane == 31) wsum[wd] = s;
    __syncthreads();
    if (wd == 0) {
        int ws = wsum[lane];
        #pragma unroll
        for (int o = 1; o < 32; o <<= 1) {
            int u = __shfl_up_sync(0xffffffffu, ws, o);
            if (lane >= o) ws += u;
        }
        wsum[lane] = ws;
        if (lane == 31) base = atomicAdd(&ctr[isW], ws);
    }
    __syncthreads();
    int excl = base + s - v + (wd > 0 ? wsum[wd - 1] : 0);
    if (i < n) {
        beg[off + i] = excl;
        cur[off + i] = excl;
        cnt[off + i] = 0;      // restore zero-invariant (line already resident)
    }
}

__global__ void place_kernel(const int* __restrict__ vidx, const int* __restrict__ eidx,
                             int* __restrict__ cur, int* __restrict__ srcx,
                             int* __restrict__ srcw, int* __restrict__ ctr,
                             int nx, int E)
{
    const int t = blockIdx.x * blockDim.x + threadIdx.x;
    if (t == 0) { ctr[0] = 0; ctr[1] = 0; }   // restore counter invariant
    const int e = t * 2;
    if (e + 1 < E) {
        int2 v2 = *(const int2*)(vidx + e);
        int2 h2 = *(const int2*)(eidx + e);
        int p1 = atomicAdd(&cur[v2.x], 1);
        srcx[p1] = h2.x;
        int p2 = atomicAdd(&cur[v2.y], 1);
        srcx[p2] = h2.y;
        int p3 = atomicAdd(&cur[nx + h2.x], 1);
        srcw[p3] = v2.x;
        int p4 = atomicAdd(&cur[nx + h2.y], 1);
        srcw[p4] = v2.y;
    } else if (e < E) {
        int v = vidx[e], hw = eidx[e];
        int p1 = atomicAdd(&cur[v], 1);
        srcx[p1] = hw;
        int p2 = atomicAdd(&cur[nx + hw], 1);
        srcw[p2] = v;
    }
}

// ---------------------------------------------------------------------------
// Segment gather-reduce: warp per segment; 8-wide predicated MLP batches.
//   acc = sum_{k in [beg[seg], end[seg])} src[lst[k]]
//   out = lin ? lin*(1+acc) : acc
// ---------------------------------------------------------------------------
__global__ void seg_reduce_kernel(const int* __restrict__ beg, const int* __restrict__ endp,
                                  const int* __restrict__ lst,
                                  const float* __restrict__ src, const float* __restrict__ lin,
                                  float* __restrict__ out, int N)
{
    const int seg  = (blockIdx.x * blockDim.x + threadIdx.x) >> 5;
    const int lane = threadIdx.x & 31;
    if (seg >= N) return;
    int k = beg[seg];
    const int end = endp[seg];
    const int j = lane * 4;
    float4 acc = make_float4(0.f, 0.f, 0.f, 0.f);

    for (; k + 8 <= end; k += 8) {
        int si[8];
        #pragma unroll
        for (int q = 0; q < 8; q++) si[q] = __ldg(&lst[k + q]);
        float4 v[8];
        #pragma unroll
        for (int q = 0; q < 8; q++)
            v[q] = *(const float4*)(src + (size_t)si[q] * D + j);
        #pragma unroll
        for (int q = 0; q < 8; q++) {
            acc.x += v[q].x; acc.y += v[q].y; acc.z += v[q].z; acc.w += v[q].w;
        }
    }
    if (k < end) {
        int si[8];
        #pragma unroll
        for (int q = 0; q < 8; q++) {
            int kk = (k + q < end) ? (k + q) : (end - 1);
            si[q] = __ldg(&lst[kk]);
        }
        float4 v[8];
        #pragma unroll
        for (int q = 0; q < 8; q++)
            v[q] = *(const float4*)(src + (size_t)si[q] * D + j);
        #pragma unroll
        for (int q = 0; q < 8; q++) {
            if (k + q < end) {
                acc.x += v[q].x; acc.y += v[q].y; acc.z += v[q].z; acc.w += v[q].w;
            }
        }
    }

    float4 o;
    if (lin != nullptr) {
        float4 l = *(const float4*)(lin + (size_t)seg * D + j);
        o.x = fmaf(acc.x, l.x, l.x);
        o.y = fmaf(acc.y, l.y, l.y);
        o.z = fmaf(acc.z, l.z, l.z);
        o.w = fmaf(acc.w, l.w, l.w);
    } else {
        o = acc;
    }
    *(float4*)(out + (size_t)seg * D + j) = o;
}

extern "C" void kernel_launch(void* const* d_in, const int* in_sizes, int n_in,
                              void* d_out, int out_size)
{
    const float* x   = (const float*)d_in[0];
    const float* w   = (const float*)d_in[1];
    const float* Wx1 = (const float*)d_in[2];
    const float* bx1 = (const float*)d_in[3];
    const float* Ww1 = (const float*)d_in[4];
    const float* bw1 = (const float*)d_in[5];
    const float* Wx2 = (const float*)d_in[6];
    const float* bx2 = (const float*)d_in[7];
    const float* Ww2 = (const float*)d_in[8];
    const float* bw2 = (const float*)d_in[9];
    const int*   h   = (const int*)d_in[10];

    const int N_X = in_sizes[0] / D;
    const int N_W = in_sizes[1] / D;
    const int E   = in_sizes[10] / 2;
    const int* vidx = h;
    const int* eidx = h + E;

    float* out_w = (float*)d_out;
    float* out_x = (float*)d_out + (size_t)N_W * D;

    float *p_xv, *p_wv, *p_we, *p_s;
    int *p_cnt, *p_beg, *p_cur, *p_srcx, *p_srcw;
    cudaGetSymbolAddress((void**)&p_xv,   g_xv);
    cudaGetSymbolAddress((void**)&p_wv,   g_wv);
    cudaGetSymbolAddress((void**)&p_we,   g_we);
    cudaGetSymbolAddress((void**)&p_s,    g_s);
    cudaGetSymbolAddress((void**)&p_cnt,  g_cnt);
    cudaGetSymbolAddress((void**)&p_beg,  g_beg);
    cudaGetSymbolAddress((void**)&p_cur,  g_cur);
    cudaGetSymbolAddress((void**)&p_srcx, g_srcx);
    cudaGetSymbolAddress((void**)&p_srcw, g_srcw);
    int* p_ctr = p_cnt + N_X + N_W;

    cudaFuncSetAttribute(gemm_hmma_kernel,
                         cudaFuncAttributeMaxDynamicSharedMemorySize, SM_TOT);

    static cudaStream_t sA = nullptr, sB = nullptr, sC = nullptr;
    static cudaEvent_t e0, eB, eA, eCv, eWV, eC;
    if (sA == nullptr) {
        cudaStreamCreateWithFlags(&sA, cudaStreamNonBlocking);
        cudaStreamCreateWithFlags(&sB, cudaStreamNonBlocking);
        cudaStreamCreateWithFlags(&sC, cudaStreamNonBlocking);
        cudaEventCreateWithFlags(&e0,  cudaEventDisableTiming);
        cudaEventCreateWithFlags(&eB,  cudaEventDisableTiming);
        cudaEventCreateWithFlags(&eA,  cudaEventDisableTiming);
        cudaEventCreateWithFlags(&eCv, cudaEventDisableTiming);
        cudaEventCreateWithFlags(&eWV, cudaEventDisableTiming);
        cudaEventCreateWithFlags(&eC,  cudaEventDisableTiming);
    }

    const int nbx = (N_X + 1023) / 1024;
    const int nbw = (N_W + 1023) / 1024;
    const int ge2 = ((E + 1) / 2 + 255) / 256;
    const int gx  = (N_X + 63) / 64;
    const int gw  = (N_W + 63) / 64;

    // fork
    cudaEventRecord(e0, 0);
    cudaStreamWaitEvent(sA, e0, 0);
    cudaStreamWaitEvent(sB, e0, 0);
    cudaStreamWaitEvent(sC, e0, 0);

    // ---- stream A: conv_w then the big xv GEMM ----
    conv_w_kernel<<<32, 256, 0, sA>>>(Ww1, Wx1, Ww2, Wx2);                    // 1
    cudaEventRecord(eCv, sA);
    gemm_hmma_kernel<<<gx, 256, SM_TOT, sA>>>(x, 1, bx1, p_xv, N_X,           // 2
                                              nullptr, nullptr, nullptr);
    cudaEventRecord(eA, sA);

    // ---- stream C: wv GEMM ----
    cudaStreamWaitEvent(sC, eCv, 0);
    gemm_hmma_kernel<<<gw, 256, SM_TOT, sC>>>(w, 0, bw1, p_wv, N_W,           // 3
                                              nullptr, nullptr, nullptr);
    cudaEventRecord(eWV, sC);

    // ---- stream B: CSR (launch 4 = hist, PROFILED) ----
    hist_kernel<<<ge2, 256, 0, sB>>>(vidx, eidx, p_cnt, N_X, E);              // 4
    offsets_kernel<<<nbx + nbw, 1024, 0, sB>>>(p_cnt, p_beg, p_cur, p_ctr,    // 5
                                               N_X, N_W, nbx);
    place_kernel<<<ge2, 256, 0, sB>>>(vidx, eidx, p_cur, p_srcx, p_srcw,      // 6
                                      p_ctr, N_X, E);
    cudaEventRecord(eB, sB);

    // ---- stream C: we GEMM ----
    gemm_hmma_kernel<<<gw, 256, SM_TOT, sC>>>(w, 2, bw2, p_we, N_W,           // 7
                                              nullptr, nullptr, nullptr);
    cudaEventRecord(eC, sC);

    // ---- sr1: out_x = xv*(1 + segsum_v(wv)) ----
    cudaStreamWaitEvent(0, eB, 0);
    cudaStreamWaitEvent(0, eA, 0);
    cudaStreamWaitEvent(0, eWV, 0);
    seg_reduce_kernel<<<(N_X + 7) / 8, 256>>>(p_beg, p_cur, p_srcx, p_wv,     // 8
                                              p_xv, out_x, N_X);

    // ---- sr2: s = segsum_e(out_x) ----
    seg_reduce_kernel<<<(N_W + 7) / 8, 256>>>(p_beg + N_X, p_cur + N_X,       // 9
                                              p_srcw, out_x, nullptr, p_s, N_W);

    // ---- final: w_new = we*(1 + s@Wx2^T + deg_w*bx2), deg = cur-beg ----
    cudaStreamWaitEvent(0, eC, 0);
    gemm_hmma_kernel<<<gw, 256, SM_TOT>>>(p_s, 3, bx2, out_w, N_W,            // 10
                                          p_beg + N_X, p_cur + N_X, p_we);
}

// round 16
// speedup vs baseline: 1.0318x; 1.0318x over previous
#include <cuda_runtime.h>
#include <cuda_bf16.h>
#include <cstring>
#include <cstdint>

// ---------------------------------------------------------------------------
// HyperEConv, HMMA bf16-split GEMMs. Converged configuration:
//   stream A: conv_w ; xv = x@Wx1^T+bx1
//   stream C: wv = w@Ww1^T+bw1 ; we = w@Ww2^T+bw2
//   stream B (serial chain): hist -> offsets -> place -> sr1 -> sr2 -> final
// Self-cleaning CSR: offsets zeros cnt after reading; place zeros counters;
// cur becomes segment END; deg = cur - beg.
// GEMM: D = Ahi*Bhi + Ahi*Blo + Alo*Bhi  (bf16 in, fp32 accum)
// Output: [w_new (N_W*128) | x_new (N_X*128)]  float32
// ---------------------------------------------------------------------------

#define MAX_NX 100000
#define MAX_NW 25000
#define MAX_E  800000
#define D 128

__device__ float g_xv [MAX_NX * D];
__device__ float g_wv [MAX_NW * D];
__device__ float g_we [MAX_NW * D];
__device__ float g_s  [MAX_NW * D];

// precomputed bf16 weights: [mat][hi=0/lo=1][2048 uint4] swizzled
__device__ uint4 g_wbf[4][2][2048];

// counts: x segs [0,NX), w segs [NX,NX+NW), 2 counters after that.
// INVARIANT: region [0, NX+NW+2) all-zero at entry of every run
// (static zero-init first run; offsets zeros cnt, place zeros counters).
__device__ int g_cnt [MAX_NX + MAX_NW + 2];
__device__ int g_beg [MAX_NX + MAX_NW];
__device__ int g_cur [MAX_NX + MAX_NW];   // after place: segment END offsets
__device__ int g_srcx[MAX_E];
__device__ int g_srcw[MAX_E];

__device__ __forceinline__ uint32_t smem_u32(const void* p) {
    uint32_t a;
    asm("{ .reg .u64 t; cvta.to.shared.u64 t, %1; cvt.u32.u64 %0, t; }"
        : "=r"(a) : "l"(p));
    return a;
}

__device__ __forceinline__ void ldmx4(uint32_t* r, uint32_t addr) {
    asm volatile("ldmatrix.sync.aligned.m8n8.x4.shared.b16 {%0,%1,%2,%3}, [%4];"
                 : "=r"(r[0]), "=r"(r[1]), "=r"(r[2]), "=r"(r[3]) : "r"(addr));
}

__device__ __forceinline__ void mma_bf16(float* d, const uint32_t* a,
                                         uint32_t b0, uint32_t b1) {
    asm volatile(
        "mma.sync.aligned.m16n8k16.row.col.f32.bf16.bf16.f32 "
        "{%0,%1,%2,%3}, {%4,%5,%6,%7}, {%8,%9}, {%0,%1,%2,%3};"
        : "+f"(d[0]), "+f"(d[1]), "+f"(d[2]), "+f"(d[3])
        : "r"(a[0]), "r"(a[1]), "r"(a[2]), "r"(a[3]), "r"(b0), "r"(b1));
}

__device__ __forceinline__ void split2(float f0, float f1, uint32_t& hi, uint32_t& lo) {
    __nv_bfloat162 hh = __floats2bfloat162_rn(f0, f1);
    float r0 = f0 - __bfloat162float(hh.x);
    float r1 = f1 - __bfloat162float(hh.y);
    __nv_bfloat162 ll = __floats2bfloat162_rn(r0, r1);
    memcpy(&hi, &hh, 4);
    memcpy(&lo, &ll, 4);
}

#define SM_AHI  0
#define SM_ALO  16384
#define SM_BHI  32768
#define SM_BLO  65536
#define SM_TOT  98304

extern __shared__ char smc[];

// ---------------------------------------------------------------------------
// Weight precompute: 4 [128x128] fp32 -> swizzled bf16 hi/lo
// ---------------------------------------------------------------------------
__global__ void conv_w_kernel(const float* __restrict__ W0, const float* __restrict__ W1,
                              const float* __restrict__ W2, const float* __restrict__ W3)
{
    const int t = blockIdx.x * blockDim.x + threadIdx.x;
    if (t >= 8192) return;
    const int mat = t >> 11;
    const int rem = t & 2047;
    const int r = rem >> 4;
    const int c = rem & 15;
    const float* Wm = (mat == 0) ? W0 : (mat == 1) ? W1 : (mat == 2) ? W2 : W3;
    const float4 u = *(const float4*)(Wm + r * 128 + c * 8);
    const float4 v = *(const float4*)(Wm + r * 128 + c * 8 + 4);
    uint4 hi, lo;
    split2(u.x, u.y, hi.x, lo.x);
    split2(u.z, u.w, hi.y, lo.y);
    split2(v.x, v.y, hi.z, lo.z);
    split2(v.z, v.w, hi.w, lo.w);
    const int off = r * 16 + (c ^ (r & 7));
    g_wbf[mat][0][off] = hi;
    g_wbf[mat][1][off] = lo;
}

__device__ __forceinline__ void load_weights_smem(int wmat, int tid) {
    const uint4* whi = g_wbf[wmat][0];
    const uint4* wlo = g_wbf[wmat][1];
    uint4* shi = (uint4*)(smc + SM_BHI);
    uint4* slo = (uint4*)(smc + SM_BLO);
    #pragma unroll
    for (int it = 0; it < 8; it++) {
        const int i = tid + it * 256;
        shi[i] = whi[i];
        slo[i] = wlo[i];
    }
}

__device__ __forceinline__ void mma_mainloop(uint32_t sb, int tid, float acc[2][4][4]) {
    const int lane = tid & 31;
    const int wid  = tid >> 5;
    const int m0 = (wid & 1) * 32;
    const int n0 = (wid >> 1) * 32;
    const int sub = lane >> 3, l8 = lane & 7;
    for (int ks = 0; ks < 8; ks++) {
        uint32_t ahi[2][4], alo[2][4], bhi[2][4], blo[2][4];
        #pragma unroll
        for (int at = 0; at < 2; at++) {
            const int ar  = m0 + at * 16 + (sub & 1) * 8 + l8;
            const int akc = ks * 2 + (sub >> 1);
            const uint32_t aoff = (uint32_t)ar * 256u + (uint32_t)((akc ^ (ar & 7)) << 4);
            ldmx4(ahi[at], sb + SM_AHI + aoff);
            ldmx4(alo[at], sb + SM_ALO + aoff);
        }
        #pragma unroll
        for (int bp = 0; bp < 2; bp++) {
            const int br  = n0 + bp * 16 + (sub >> 1) * 8 + l8;
            const int bkc = ks * 2 + (sub & 1);
            const uint32_t boff = (uint32_t)br * 256u + (uint32_t)((bkc ^ (br & 7)) << 4);
            ldmx4(bhi[bp], sb + SM_BHI + boff);
            ldmx4(blo[bp], sb + SM_BLO + boff);
        }
        #pragma unroll
        for (int at = 0; at < 2; at++) {
            #pragma unroll
            for (int nt = 0; nt < 4; nt++) {
                const int bp = nt >> 1, o = (nt & 1) * 2;
                mma_bf16(acc[at][nt], ahi[at], bhi[bp][o], bhi[bp][o + 1]);
                mma_bf16(acc[at][nt], ahi[at], blo[bp][o], blo[bp][o + 1]);
                mma_bf16(acc[at][nt], alo[at], bhi[bp][o], bhi[bp][o + 1]);
            }
        }
    }
}

// ---------------------------------------------------------------------------
// HMMA GEMM: v = A@W^T + bias*deg ; deg = degE[r]-degB[r] (1 if degB null)
//   out = mul ? mul*(1+v) : v
// 256 threads, 64-row tile per CTA, warps 2(m) x 4(n), 96KB smem -> 2 CTAs/SM.
// ---------------------------------------------------------------------------
__global__ void __launch_bounds__(256, 2)
gemm_hmma_kernel(const float* __restrict__ A, int wmat,
                 const float* __restrict__ bias, float* __restrict__ C, int M,
                 const int* __restrict__ degB, const int* __restrict__ degE,
                 const float* __restrict__ mulSrc)
{
    const uint32_t sb = smem_u32(smc);
    const int tid = threadIdx.x;
    const int lane = tid & 31;
    const int wid  = tid >> 5;
    const int rowBase = blockIdx.x * 64;

    load_weights_smem(wmat, tid);

    #pragma unroll
    for (int it = 0; it < 4; it++) {
        const int task = tid + it * 256;
        const int r = task >> 4;
        const int c = task & 15;
        const int grow = rowBase + r;
        float4 u = make_float4(0.f, 0.f, 0.f, 0.f), v = u;
        if (grow < M) {
            const float* Ar = A + (size_t)grow * D + c * 8;
            u = *(const float4*)Ar;
            v = *(const float4*)(Ar + 4);
        }
        uint4 hi, lo;
        split2(u.x, u.y, hi.x, lo.x);
        split2(u.z, u.w, hi.y, lo.y);
        split2(v.x, v.y, hi.z, lo.z);
        split2(v.z, v.w, hi.w, lo.w);
        const uint32_t off = (uint32_t)r * 256u + (uint32_t)((c ^ (r & 7)) << 4);
        *(uint4*)(smc + SM_AHI + off) = hi;
        *(uint4*)(smc + SM_ALO + off) = lo;
    }
    __syncthreads();

    float acc[2][4][4];
    #pragma unroll
    for (int at = 0; at < 2; at++)
        #pragma unroll
        for (int nt = 0; nt < 4; nt++)
            #pragma unroll
            for (int q = 0; q < 4; q++) acc[at][nt][q] = 0.f;

    mma_mainloop(sb, tid, acc);

    const int m0 = (wid & 1) * 32;
    const int n0 = (wid >> 1) * 32;
    const bool hasMul = (mulSrc != nullptr);
    #pragma unroll
    for (int at = 0; at < 2; at++) {
        const int rA = rowBase + m0 + at * 16 + (lane >> 2);
        const int rB = rA + 8;
        float dA = 1.f, dB = 1.f;
        if (degB != nullptr) {
            if (rA < M) dA = (float)(degE[rA] - degB[rA]);
            if (rB < M) dB = (float)(degE[rB] - degB[rB]);
        }
        #pragma unroll
        for (int nt = 0; nt < 4; nt++) {
            const int col = n0 + nt * 8 + (lane & 3) * 2;
            const float2 b2 = *(const float2*)(bias + col);
            if (rA < M) {
                float v0 = acc[at][nt][0] + b2.x * dA;
                float v1 = acc[at][nt][1] + b2.y * dA;
                if (hasMul) {
                    float2 m = *(const float2*)(mulSrc + (size_t)rA * D + col);
                    v0 = fmaf(m.x, v0, m.x);
                    v1 = fmaf(m.y, v1, m.y);
                }
                *(float2*)(C + (size_t)rA * D + col) = make_float2(v0, v1);
            }
            if (rB < M) {
                float v0 = acc[at][nt][2] + b2.x * dB;
                float v1 = acc[at][nt][3] + b2.y * dB;
                if (hasMul) {
                    float2 m = *(const float2*)(mulSrc + (size_t)rB * D + col);
                    v0 = fmaf(m.x, v0, m.x);
                    v1 = fmaf(m.y, v1, m.y);
                }
                *(float2*)(C + (size_t)rB * D + col) = make_float2(v0, v1);
            }
        }
    }
}

// ---------------------------------------------------------------------------
// CSR build (both directions per kernel); self-cleaning; scalar (measured best)
// ---------------------------------------------------------------------------
__global__ void hist_kernel(const int* __restrict__ vidx, const int* __restrict__ eidx,
                            int* __restrict__ cnt, int nx, int E)
{
    int e = blockIdx.x * blockDim.x + threadIdx.x;
    if (e < E) {
        atomicAdd(&cnt[vidx[e]], 1);
        atomicAdd(&cnt[nx + eidx[e]], 1);
    }
}

// per-block scan + atomic base grab; zeros cnt after reading (invariant restore)
__global__ void __launch_bounds__(1024)
offsets_kernel(int* __restrict__ cnt, int* __restrict__ beg,
               int* __restrict__ cur, int* __restrict__ ctr,
               int nx, int nw, int nbx)
{
    const int isW = (blockIdx.x >= nbx) ? 1 : 0;
    const int blk = isW ? (blockIdx.x - nbx) : blockIdx.x;
    const int n   = isW ? nw : nx;
    const int off = isW ? nx : 0;

    const int t = threadIdx.x;
    const int i = blk * 1024 + t;
    int v = (i < n) ? cnt[off + i] : 0;

    const int lane = t & 31, wd = t >> 5;
    int s = v;
    #pragma unroll
    for (int o = 1; o < 32; o <<= 1) {
        int u = __shfl_up_sync(0xffffffffu, s, o);
        if (lane >= o) s += u;
    }
    __shared__ int wsum[32];
    __shared__ int base;
    if (lane == 31) wsum[wd] = s;
    __syncthreads();
    if (wd == 0) {
        int ws = wsum[lane];
        #pragma unroll
        for (int o = 1; o < 32; o <<= 1) {
            int u = __shfl_up_sync(0xffffffffu, ws, o);
            if (lane >= o) ws += u;
        }
        wsum[lane] = ws;
        if (lane == 31) base = atomicAdd(&ctr[isW], ws);
    }
    __syncthreads();
    int excl = base + s - v + (wd > 0 ? wsum[wd - 1] : 0);
    if (i < n) {
        beg[off + i] = excl;
        cur[off + i] = excl;
        cnt[off + i] = 0;      // restore zero-invariant (line already resident)
    }
}

__global__ void place_kernel(const int* __restrict__ vidx, const int* __restrict__ eidx,
                             int* __restrict__ cur, int* __restrict__ srcx,
                             int* __restrict__ srcw, int* __restrict__ ctr,
                             int nx, int E)
{
    int e = blockIdx.x * blockDim.x + threadIdx.x;
    if (e == 0) { ctr[0] = 0; ctr[1] = 0; }   // restore counter invariant
    if (e < E) {
        int v = vidx[e], hw = eidx[e];
        int p1 = atomicAdd(&cur[v], 1);
        srcx[p1] = hw;
        int p2 = atomicAdd(&cur[nx + hw], 1);
        srcw[p2] = v;
    }
}

// ---------------------------------------------------------------------------
// Segment gather-reduce: warp per segment; 8-wide predicated MLP batches.
//   acc = sum_{k in [beg[seg], end[seg])} src[lst[k]]
//   out = lin ? lin*(1+acc) : acc
// ---------------------------------------------------------------------------
__global__ void seg_reduce_kernel(const int* __restrict__ beg, const int* __restrict__ endp,
                                  const int* __restrict__ lst,
                                  const float* __restrict__ src, const float* __restrict__ lin,
                                  float* __restrict__ out, int N)
{
    const int seg  = (blockIdx.x * blockDim.x + threadIdx.x) >> 5;
    const int lane = threadIdx.x & 31;
    if (seg >= N) return;
    int k = beg[seg];
    const int end = endp[seg];
    const int j = lane * 4;
    float4 acc = make_float4(0.f, 0.f, 0.f, 0.f);

    for (; k + 8 <= end; k += 8) {
        int si[8];
        #pragma unroll
        for (int q = 0; q < 8; q++) si[q] = __ldg(&lst[k + q]);
        float4 v[8];
        #pragma unroll
        for (int q = 0; q < 8; q++)
            v[q] = *(const float4*)(src + (size_t)si[q] * D + j);
        #pragma unroll
        for (int q = 0; q < 8; q++) {
            acc.x += v[q].x; acc.y += v[q].y; acc.z += v[q].z; acc.w += v[q].w;
        }
    }
    if (k < end) {
        int si[8];
        #pragma unroll
        for (int q = 0; q < 8; q++) {
            int kk = (k + q < end) ? (k + q) : (end - 1);
            si[q] = __ldg(&lst[kk]);
        }
        float4 v[8];
        #pragma unroll
        for (int q = 0; q < 8; q++)
            v[q] = *(const float4*)(src + (size_t)si[q] * D + j);
        #pragma unroll
        for (int q = 0; q < 8; q++) {
            if (k + q < end) {
                acc.x += v[q].x; acc.y += v[q].y; acc.z += v[q].z; acc.w += v[q].w;
            }
        }
    }

    float4 o;
    if (lin != nullptr) {
        float4 l = *(const float4*)(lin + (size_t)seg * D + j);
        o.x = fmaf(acc.x, l.x, l.x);
        o.y = fmaf(acc.y, l.y, l.y);
        o.z = fmaf(acc.z, l.z, l.z);
        o.w = fmaf(acc.w, l.w, l.w);
    } else {
        o = acc;
    }
    *(float4*)(out + (size_t)seg * D + j) = o;
}

extern "C" void kernel_launch(void* const* d_in, const int* in_sizes, int n_in,
                              void* d_out, int out_size)
{
    const float* x   = (const float*)d_in[0];
    const float* w   = (const float*)d_in[1];
    const float* Wx1 = (const float*)d_in[2];
    const float* bx1 = (const float*)d_in[3];
    const float* Ww1 = (const float*)d_in[4];
    const float* bw1 = (const float*)d_in[5];
    const float* Wx2 = (const float*)d_in[6];
    const float* bx2 = (const float*)d_in[7];
    const float* Ww2 = (const float*)d_in[8];
    const float* bw2 = (const float*)d_in[9];
    const int*   h   = (const int*)d_in[10];

    const int N_X = in_sizes[0] / D;
    const int N_W = in_sizes[1] / D;
    const int E   = in_sizes[10] / 2;
    const int* vidx = h;
    const int* eidx = h + E;

    float* out_w = (float*)d_out;
    float* out_x = (float*)d_out + (size_t)N_W * D;

    float *p_xv, *p_wv, *p_we, *p_s;
    int *p_cnt, *p_beg, *p_cur, *p_srcx, *p_srcw;
    cudaGetSymbolAddress((void**)&p_xv,   g_xv);
    cudaGetSymbolAddress((void**)&p_wv,   g_wv);
    cudaGetSymbolAddress((void**)&p_we,   g_we);
    cudaGetSymbolAddress((void**)&p_s,    g_s);
    cudaGetSymbolAddress((void**)&p_cnt,  g_cnt);
    cudaGetSymbolAddress((void**)&p_beg,  g_beg);
    cudaGetSymbolAddress((void**)&p_cur,  g_cur);
    cudaGetSymbolAddress((void**)&p_srcx, g_srcx);
    cudaGetSymbolAddress((void**)&p_srcw, g_srcw);
    int* p_ctr = p_cnt + N_X + N_W;

    cudaFuncSetAttribute(gemm_hmma_kernel,
                         cudaFuncAttributeMaxDynamicSharedMemorySize, SM_TOT);

    static cudaStream_t sA = nullptr, sB = nullptr, sC = nullptr;
    static cudaEvent_t e0, eA, eCv, eWV, eC;
    if (sA == nullptr) {
        cudaStreamCreateWithFlags(&sA, cudaStreamNonBlocking);
        cudaStreamCreateWithFlags(&sB, cudaStreamNonBlocking);
        cudaStreamCreateWithFlags(&sC, cudaStreamNonBlocking);
        cudaEventCreateWithFlags(&e0,  cudaEventDisableTiming);
        cudaEventCreateWithFlags(&eA,  cudaEventDisableTiming);
        cudaEventCreateWithFlags(&eCv, cudaEventDisableTiming);
        cudaEventCreateWithFlags(&eWV, cudaEventDisableTiming);
        cudaEventCreateWithFlags(&eC,  cudaEventDisableTiming);
    }

    const int nbx = (N_X + 1023) / 1024;
    const int nbw = (N_W + 1023) / 1024;
    const int ge  = (E + 255) / 256;
    const int gx  = (N_X + 63) / 64;
    const int gw  = (N_W + 63) / 64;

    // fork
    cudaEventRecord(e0, 0);
    cudaStreamWaitEvent(sA, e0, 0);
    cudaStreamWaitEvent(sB, e0, 0);
    cudaStreamWaitEvent(sC, e0, 0);

    // ---- stream A: conv_w then the big xv GEMM ----
    conv_w_kernel<<<32, 256, 0, sA>>>(Ww1, Wx1, Ww2, Wx2);                    // 1
    cudaEventRecord(eCv, sA);
    gemm_hmma_kernel<<<gx, 256, SM_TOT, sA>>>(x, 1, bx1, p_xv, N_X,           // 2
                                              nullptr, nullptr, nullptr);
    cudaEventRecord(eA, sA);

    // ---- stream C: wv + we GEMMs ----
    cudaStreamWaitEvent(sC, eCv, 0);
    gemm_hmma_kernel<<<gw, 256, SM_TOT, sC>>>(w, 0, bw1, p_wv, N_W,           // 3
                                              nullptr, nullptr, nullptr);
    cudaEventRecord(eWV, sC);

    // ---- stream B: full serial chain (no eB join needed) ----
    hist_kernel<<<ge, 256, 0, sB>>>(vidx, eidx, p_cnt, N_X, E);               // 4
    offsets_kernel<<<nbx + nbw, 1024, 0, sB>>>(p_cnt, p_beg, p_cur, p_ctr,    // 5
                                               N_X, N_W, nbx);
    place_kernel<<<ge, 256, 0, sB>>>(vidx, eidx, p_cur, p_srcx, p_srcw,       // 6
                                     p_ctr, N_X, E);

    gemm_hmma_kernel<<<gw, 256, SM_TOT, sC>>>(w, 2, bw2, p_we, N_W,           // 7
                                              nullptr, nullptr, nullptr);
    cudaEventRecord(eC, sC);

    // ---- sr1 on stream B: out_x = xv*(1 + segsum_v(wv)) ----
    cudaStreamWaitEvent(sB, eA, 0);
    cudaStreamWaitEvent(sB, eWV, 0);
    seg_reduce_kernel<<<(N_X + 7) / 8, 256, 0, sB>>>(p_beg, p_cur, p_srcx,    // 8
                                                     p_wv, p_xv, out_x, N_X);

    // ---- sr2 on stream B: s = segsum_e(out_x) ----
    seg_reduce_kernel<<<(N_W + 7) / 8, 256, 0, sB>>>(p_beg + N_X, p_cur + N_X,// 9
                                                     p_srcw, out_x, nullptr,
                                                     p_s, N_W);

    // ---- final on stream B: w_new = we*(1 + s@Wx2^T + deg_w*bx2) ----
    cudaStreamWaitEvent(sB, eC, 0);
    gemm_hmma_kernel<<<gw, 256, SM_TOT, sB>>>(p_s, 3, bx2, out_w, N_W,        // 10
                                              p_beg + N_X, p_cur + N_X, p_we);

    // join stream B back to the capture (legacy) stream
    cudaEventRecord(e0, sB);
    cudaStreamWaitEvent(0, e0, 0);
}

// round 17
// speedup vs baseline: 1.0691x; 1.0361x over previous
#include <cuda_runtime.h>
#include <cuda_bf16.h>
#include <cstring>
#include <cstdint>

// ---------------------------------------------------------------------------
// HyperEConv, HMMA bf16-split GEMMs. Split-place configuration:
//   stream A: conv_w ; xv = x@Wx1^T+bx1
//   stream C: wv = w@Ww1^T+bw1 ; place_w (after offsets) ; we = w@Ww2^T+bw2
//   stream B (serial chain): hist -> offsets -> place_x -> sr1 -> sr2 -> final
// Self-cleaning CSR: offsets zeros cnt after reading; place_w zeros counters;
// cur becomes segment END; deg = cur - beg.
// GEMM: D = Ahi*Bhi + Ahi*Blo + Alo*Bhi  (bf16 in, fp32 accum)
// Output: [w_new (N_W*128) | x_new (N_X*128)]  float32
// ---------------------------------------------------------------------------

#define MAX_NX 100000
#define MAX_NW 25000
#define MAX_E  800000
#define D 128

__device__ float g_xv [MAX_NX * D];
__device__ float g_wv [MAX_NW * D];
__device__ float g_we [MAX_NW * D];
__device__ float g_s  [MAX_NW * D];

// precomputed bf16 weights: [mat][hi=0/lo=1][2048 uint4] swizzled
__device__ uint4 g_wbf[4][2][2048];

// counts: x segs [0,NX), w segs [NX,NX+NW), 2 counters after that.
// INVARIANT: region [0, NX+NW+2) all-zero at entry of every run
// (static zero-init first run; offsets zeros cnt, place_w zeros counters).
__device__ int g_cnt [MAX_NX + MAX_NW + 2];
__device__ int g_beg [MAX_NX + MAX_NW];
__device__ int g_cur [MAX_NX + MAX_NW];   // after place_*: segment END offsets
__device__ int g_srcx[MAX_E];
__device__ int g_srcw[MAX_E];

__device__ __forceinline__ uint32_t smem_u32(const void* p) {
    uint32_t a;
    asm("{ .reg .u64 t; cvta.to.shared.u64 t, %1; cvt.u32.u64 %0, t; }"
        : "=r"(a) : "l"(p));
    return a;
}

__device__ __forceinline__ void ldmx4(uint32_t* r, uint32_t addr) {
    asm volatile("ldmatrix.sync.aligned.m8n8.x4.shared.b16 {%0,%1,%2,%3}, [%4];"
                 : "=r"(r[0]), "=r"(r[1]), "=r"(r[2]), "=r"(r[3]) : "r"(addr));
}

__device__ __forceinline__ void mma_bf16(float* d, const uint32_t* a,
                                         uint32_t b0, uint32_t b1) {
    asm volatile(
        "mma.sync.aligned.m16n8k16.row.col.f32.bf16.bf16.f32 "
        "{%0,%1,%2,%3}, {%4,%5,%6,%7}, {%8,%9}, {%0,%1,%2,%3};"
        : "+f"(d[0]), "+f"(d[1]), "+f"(d[2]), "+f"(d[3])
        : "r"(a[0]), "r"(a[1]), "r"(a[2]), "r"(a[3]), "r"(b0), "r"(b1));
}

__device__ __forceinline__ void split2(float f0, float f1, uint32_t& hi, uint32_t& lo) {
    __nv_bfloat162 hh = __floats2bfloat162_rn(f0, f1);
    float r0 = f0 - __bfloat162float(hh.x);
    float r1 = f1 - __bfloat162float(hh.y);
    __nv_bfloat162 ll = __floats2bfloat162_rn(r0, r1);
    memcpy(&hi, &hh, 4);
    memcpy(&lo, &ll, 4);
}

#define SM_AHI  0
#define SM_ALO  16384
#define SM_BHI  32768
#define SM_BLO  65536
#define SM_TOT  98304

extern __shared__ char smc[];

// ---------------------------------------------------------------------------
// Weight precompute: 4 [128x128] fp32 -> swizzled bf16 hi/lo
// ---------------------------------------------------------------------------
__global__ void conv_w_kernel(const float* __restrict__ W0, const float* __restrict__ W1,
                              const float* __restrict__ W2, const float* __restrict__ W3)
{
    const int t = blockIdx.x * blockDim.x + threadIdx.x;
    if (t >= 8192) return;
    const int mat = t >> 11;
    const int rem = t & 2047;
    const int r = rem >> 4;
    const int c = rem & 15;
    const float* Wm = (mat == 0) ? W0 : (mat == 1) ? W1 : (mat == 2) ? W2 : W3;
    const float4 u = *(const float4*)(Wm + r * 128 + c * 8);
    const float4 v = *(const float4*)(Wm + r * 128 + c * 8 + 4);
    uint4 hi, lo;
    split2(u.x, u.y, hi.x, lo.x);
    split2(u.z, u.w, hi.y, lo.y);
    split2(v.x, v.y, hi.z, lo.z);
    split2(v.z, v.w, hi.w, lo.w);
    const int off = r * 16 + (c ^ (r & 7));
    g_wbf[mat][0][off] = hi;
    g_wbf[mat][1][off] = lo;
}

__device__ __forceinline__ void load_weights_smem(int wmat, int tid) {
    const uint4* whi = g_wbf[wmat][0];
    const uint4* wlo = g_wbf[wmat][1];
    uint4* shi = (uint4*)(smc + SM_BHI);
    uint4* slo = (uint4*)(smc + SM_BLO);
    #pragma unroll
    for (int it = 0; it < 8; it++) {
        const int i = tid + it * 256;
        shi[i] = whi[i];
        slo[i] = wlo[i];
    }
}

__device__ __forceinline__ void mma_mainloop(uint32_t sb, int tid, float acc[2][4][4]) {
    const int lane = tid & 31;
    const int wid  = tid >> 5;
    const int m0 = (wid & 1) * 32;
    const int n0 = (wid >> 1) * 32;
    const int sub = lane >> 3, l8 = lane & 7;
    for (int ks = 0; ks < 8; ks++) {
        uint32_t ahi[2][4], alo[2][4], bhi[2][4], blo[2][4];
        #pragma unroll
        for (int at = 0; at < 2; at++) {
            const int ar  = m0 + at * 16 + (sub & 1) * 8 + l8;
            const int akc = ks * 2 + (sub >> 1);
            const uint32_t aoff = (uint32_t)ar * 256u + (uint32_t)((akc ^ (ar & 7)) << 4);
            ldmx4(ahi[at], sb + SM_AHI + aoff);
            ldmx4(alo[at], sb + SM_ALO + aoff);
        }
        #pragma unroll
        for (int bp = 0; bp < 2; bp++) {
            const int br  = n0 + bp * 16 + (sub >> 1) * 8 + l8;
            const int bkc = ks * 2 + (sub & 1);
            const uint32_t boff = (uint32_t)br * 256u + (uint32_t)((bkc ^ (br & 7)) << 4);
            ldmx4(bhi[bp], sb + SM_BHI + boff);
            ldmx4(blo[bp], sb + SM_BLO + boff);
        }
        #pragma unroll
        for (int at = 0; at < 2; at++) {
            #pragma unroll
            for (int nt = 0; nt < 4; nt++) {
                const int bp = nt >> 1, o = (nt & 1) * 2;
                mma_bf16(acc[at][nt], ahi[at], bhi[bp][o], bhi[bp][o + 1]);
                mma_bf16(acc[at][nt], ahi[at], blo[bp][o], blo[bp][o + 1]);
                mma_bf16(acc[at][nt], alo[at], bhi[bp][o], bhi[bp][o + 1]);
            }
        }
    }
}

// ---------------------------------------------------------------------------
// HMMA GEMM: v = A@W^T + bias*deg ; deg = degE[r]-degB[r] (1 if degB null)
//   out = mul ? mul*(1+v) : v
// ---------------------------------------------------------------------------
__global__ void __launch_bounds__(256, 2)
gemm_hmma_kernel(const float* __restrict__ A, int wmat,
                 const float* __restrict__ bias, float* __restrict__ C, int M,
                 const int* __restrict__ degB, const int* __restrict__ degE,
                 const float* __restrict__ mulSrc)
{
    const uint32_t sb = smem_u32(smc);
    const int tid = threadIdx.x;
    const int lane = tid & 31;
    const int wid  = tid >> 5;
    const int rowBase = blockIdx.x * 64;

    load_weights_smem(wmat, tid);

    #pragma unroll
    for (int it = 0; it < 4; it++) {
        const int task = tid + it * 256;
        const int r = task >> 4;
        const int c = task & 15;
        const int grow = rowBase + r;
        float4 u = make_float4(0.f, 0.f, 0.f, 0.f), v = u;
        if (grow < M) {
            const float* Ar = A + (size_t)grow * D + c * 8;
            u = *(const float4*)Ar;
            v = *(const float4*)(Ar + 4);
        }
        uint4 hi, lo;
        split2(u.x, u.y, hi.x, lo.x);
        split2(u.z, u.w, hi.y, lo.y);
        split2(v.x, v.y, hi.z, lo.z);
        split2(v.z, v.w, hi.w, lo.w);
        const uint32_t off = (uint32_t)r * 256u + (uint32_t)((c ^ (r & 7)) << 4);
        *(uint4*)(smc + SM_AHI + off) = hi;
        *(uint4*)(smc + SM_ALO + off) = lo;
    }
    __syncthreads();

    float acc[2][4][4];
    #pragma unroll
    for (int at = 0; at < 2; at++)
        #pragma unroll
        for (int nt = 0; nt < 4; nt++)
            #pragma unroll
            for (int q = 0; q < 4; q++) acc[at][nt][q] = 0.f;

    mma_mainloop(sb, tid, acc);

    const int m0 = (wid & 1) * 32;
    const int n0 = (wid >> 1) * 32;
    const bool hasMul = (mulSrc != nullptr);
    #pragma unroll
    for (int at = 0; at < 2; at++) {
        const int rA = rowBase + m0 + at * 16 + (lane >> 2);
        const int rB = rA + 8;
        float dA = 1.f, dB = 1.f;
        if (degB != nullptr) {
            if (rA < M) dA = (float)(degE[rA] - degB[rA]);
            if (rB < M) dB = (float)(degE[rB] - degB[rB]);
        }
        #pragma unroll
        for (int nt = 0; nt < 4; nt++) {
            const int col = n0 + nt * 8 + (lane & 3) * 2;
            const float2 b2 = *(const float2*)(bias + col);
            if (rA < M) {
                float v0 = acc[at][nt][0] + b2.x * dA;
                float v1 = acc[at][nt][1] + b2.y * dA;
                if (hasMul) {
                    float2 m = *(const float2*)(mulSrc + (size_t)rA * D + col);
                    v0 = fmaf(m.x, v0, m.x);
                    v1 = fmaf(m.y, v1, m.y);
                }
                *(float2*)(C + (size_t)rA * D + col) = make_float2(v0, v1);
            }
            if (rB < M) {
                float v0 = acc[at][nt][2] + b2.x * dB;
                float v1 = acc[at][nt][3] + b2.y * dB;
                if (hasMul) {
                    float2 m = *(const float2*)(mulSrc + (size_t)rB * D + col);
                    v0 = fmaf(m.x, v0, m.x);
                    v1 = fmaf(m.y, v1, m.y);
                }
                *(float2*)(C + (size_t)rB * D + col) = make_float2(v0, v1);
            }
        }
    }
}

// ---------------------------------------------------------------------------
// CSR build; self-cleaning; place split per direction.
// ---------------------------------------------------------------------------
__global__ void hist_kernel(const int* __restrict__ vidx, const int* __restrict__ eidx,
                            int* __restrict__ cnt, int nx, int E)
{
    int e = blockIdx.x * blockDim.x + threadIdx.x;
    if (e < E) {
        atomicAdd(&cnt[vidx[e]], 1);
        atomicAdd(&cnt[nx + eidx[e]], 1);
    }
}

// per-block scan + atomic base grab; zeros cnt after reading (invariant restore)
__global__ void __launch_bounds__(1024)
offsets_kernel(int* __restrict__ cnt, int* __restrict__ beg,
               int* __restrict__ cur, int* __restrict__ ctr,
               int nx, int nw, int nbx)
{
    const int isW = (blockIdx.x >= nbx) ? 1 : 0;
    const int blk = isW ? (blockIdx.x - nbx) : blockIdx.x;
    const int n   = isW ? nw : nx;
    const int off = isW ? nx : 0;

    const int t = threadIdx.x;
    const int i = blk * 1024 + t;
    int v = (i < n) ? cnt[off + i] : 0;

    const int lane = t & 31, wd = t >> 5;
    int s = v;
    #pragma unroll
    for (int o = 1; o < 32; o <<= 1) {
        int u = __shfl_up_sync(0xffffffffu, s, o);
        if (lane >= o) s += u;
    }
    __shared__ int wsum[32];
    __shared__ int base;
    if (lane == 31) wsum[wd] = s;
    __syncthreads();
    if (wd == 0) {
        int ws = wsum[lane];
        #pragma unroll
        for (int o = 1; o < 32; o <<= 1) {
            int u = __shfl_up_sync(0xffffffffu, ws, o);
            if (lane >= o) ws += u;
        }
        wsum[lane] = ws;
        if (lane == 31) base = atomicAdd(&ctr[isW], ws);
    }
    __syncthreads();
    int excl = base + s - v + (wd > 0 ? wsum[wd - 1] : 0);
    if (i < n) {
        beg[off + i] = excl;
        cur[off + i] = excl;
        cnt[off + i] = 0;      // restore zero-invariant (line already resident)
    }
}

// x-direction placement only (sr1's sole CSR dependency)
__global__ void place_x_kernel(const int* __restrict__ vidx, const int* __restrict__ eidx,
                               int* __restrict__ cur, int* __restrict__ srcx, int E)
{
    int e = blockIdx.x * blockDim.x + threadIdx.x;
    if (e < E) {
        int p = atomicAdd(&cur[vidx[e]], 1);
        srcx[p] = eidx[e];
    }
}

// w-direction placement; also restores counter invariant
__global__ void place_w_kernel(const int* __restrict__ vidx, const int* __restrict__ eidx,
                               int* __restrict__ cur, int* __restrict__ srcw,
                               int* __restrict__ ctr, int nx, int E)
{
    int e = blockIdx.x * blockDim.x + threadIdx.x;
    if (e == 0) { ctr[0] = 0; ctr[1] = 0; }
    if (e < E) {
        int p = atomicAdd(&cur[nx + eidx[e]], 1);
        srcw[p] = vidx[e];
    }
}

// ---------------------------------------------------------------------------
// Segment gather-reduce: warp per segment; 8-wide predicated MLP batches.
//   acc = sum_{k in [beg[seg], end[seg])} src[lst[k]]
//   out = lin ? lin*(1+acc) : acc
// ---------------------------------------------------------------------------
__global__ void seg_reduce_kernel(const int* __restrict__ beg, const int* __restrict__ endp,
                                  const int* __restrict__ lst,
                                  const float* __restrict__ src, const float* __restrict__ lin,
                                  float* __restrict__ out, int N)
{
    const int seg  = (blockIdx.x * blockDim.x + threadIdx.x) >> 5;
    const int lane = threadIdx.x & 31;
    if (seg >= N) return;
    int k = beg[seg];
    const int end = endp[seg];
    const int j = lane * 4;
    float4 acc = make_float4(0.f, 0.f, 0.f, 0.f);

    for (; k + 8 <= end; k += 8) {
        int si[8];
        #pragma unroll
        for (int q = 0; q < 8; q++) si[q] = __ldg(&lst[k + q]);
        float4 v[8];
        #pragma unroll
        for (int q = 0; q < 8; q++)
            v[q] = *(const float4*)(src + (size_t)si[q] * D + j);
        #pragma unroll
        for (int q = 0; q < 8; q++) {
            acc.x += v[q].x; acc.y += v[q].y; acc.z += v[q].z; acc.w += v[q].w;
        }
    }
    if (k < end) {
        int si[8];
        #pragma unroll
        for (int q = 0; q < 8; q++) {
            int kk = (k + q < end) ? (k + q) : (end - 1);
            si[q] = __ldg(&lst[kk]);
        }
        float4 v[8];
        #pragma unroll
        for (int q = 0; q < 8; q++)
            v[q] = *(const float4*)(src + (size_t)si[q] * D + j);
        #pragma unroll
        for (int q = 0; q < 8; q++) {
            if (k + q < end) {
                acc.x += v[q].x; acc.y += v[q].y; acc.z += v[q].z; acc.w += v[q].w;
            }
        }
    }

    float4 o;
    if (lin != nullptr) {
        float4 l = *(const float4*)(lin + (size_t)seg * D + j);
        o.x = fmaf(acc.x, l.x, l.x);
        o.y = fmaf(acc.y, l.y, l.y);
        o.z = fmaf(acc.z, l.z, l.z);
        o.w = fmaf(acc.w, l.w, l.w);
    } else {
        o = acc;
    }
    *(float4*)(out + (size_t)seg * D + j) = o;
}

extern "C" void kernel_launch(void* const* d_in, const int* in_sizes, int n_in,
                              void* d_out, int out_size)
{
    const float* x   = (const float*)d_in[0];
    const float* w   = (const float*)d_in[1];
    const float* Wx1 = (const float*)d_in[2];
    const float* bx1 = (const float*)d_in[3];
    const float* Ww1 = (const float*)d_in[4];
    const float* bw1 = (const float*)d_in[5];
    const float* Wx2 = (const float*)d_in[6];
    const float* bx2 = (const float*)d_in[7];
    const float* Ww2 = (const float*)d_in[8];
    const float* bw2 = (const float*)d_in[9];
    const int*   h   = (const int*)d_in[10];

    const int N_X = in_sizes[0] / D;
    const int N_W = in_sizes[1] / D;
    const int E   = in_sizes[10] / 2;
    const int* vidx = h;
    const int* eidx = h + E;

    float* out_w = (float*)d_out;
    float* out_x = (float*)d_out + (size_t)N_W * D;

    float *p_xv, *p_wv, *p_we, *p_s;
    int *p_cnt, *p_beg, *p_cur, *p_srcx, *p_srcw;
    cudaGetSymbolAddress((void**)&p_xv,   g_xv);
    cudaGetSymbolAddress((void**)&p_wv,   g_wv);
    cudaGetSymbolAddress((void**)&p_we,   g_we);
    cudaGetSymbolAddress((void**)&p_s,    g_s);
    cudaGetSymbolAddress((void**)&p_cnt,  g_cnt);
    cudaGetSymbolAddress((void**)&p_beg,  g_beg);
    cudaGetSymbolAddress((void**)&p_cur,  g_cur);
    cudaGetSymbolAddress((void**)&p_srcx, g_srcx);
    cudaGetSymbolAddress((void**)&p_srcw, g_srcw);
    int* p_ctr = p_cnt + N_X + N_W;

    cudaFuncSetAttribute(gemm_hmma_kernel,
                         cudaFuncAttributeMaxDynamicSharedMemorySize, SM_TOT);

    static cudaStream_t sA = nullptr, sB = nullptr, sC = nullptr;
    static cudaEvent_t e0, eA, eCv, eWV, eC, eOff, ePW, eEnd;
    if (sA == nullptr) {
        cudaStreamCreateWithFlags(&sA, cudaStreamNonBlocking);
        cudaStreamCreateWithFlags(&sB, cudaStreamNonBlocking);
        cudaStreamCreateWithFlags(&sC, cudaStreamNonBlocking);
        cudaEventCreateWithFlags(&e0,   cudaEventDisableTiming);
        cudaEventCreateWithFlags(&eA,   cudaEventDisableTiming);
        cudaEventCreateWithFlags(&eCv,  cudaEventDisableTiming);
        cudaEventCreateWithFlags(&eWV,  cudaEventDisableTiming);
        cudaEventCreateWithFlags(&eC,   cudaEventDisableTiming);
        cudaEventCreateWithFlags(&eOff, cudaEventDisableTiming);
        cudaEventCreateWithFlags(&ePW,  cudaEventDisableTiming);
        cudaEventCreateWithFlags(&eEnd, cudaEventDisableTiming);
    }

    const int nbx = (N_X + 1023) / 1024;
    const int nbw = (N_W + 1023) / 1024;
    const int ge  = (E + 255) / 256;
    const int gx  = (N_X + 63) / 64;
    const int gw  = (N_W + 63) / 64;

    // fork
    cudaEventRecord(e0, 0);
    cudaStreamWaitEvent(sA, e0, 0);
    cudaStreamWaitEvent(sB, e0, 0);
    cudaStreamWaitEvent(sC, e0, 0);

    // ---- stream A: conv_w then the big xv GEMM ----
    conv_w_kernel<<<32, 256, 0, sA>>>(Ww1, Wx1, Ww2, Wx2);                    // 1
    cudaEventRecord(eCv, sA);
    gemm_hmma_kernel<<<gx, 256, SM_TOT, sA>>>(x, 1, bx1, p_xv, N_X,           // 2
                                              nullptr, nullptr, nullptr);
    cudaEventRecord(eA, sA);

    // ---- stream C: wv GEMM ----
    cudaStreamWaitEvent(sC, eCv, 0);
    gemm_hmma_kernel<<<gw, 256, SM_TOT, sC>>>(w, 0, bw1, p_wv, N_W,           // 3
                                              nullptr, nullptr, nullptr);
    cudaEventRecord(eWV, sC);

    // ---- stream B: shortened serial chain ----
    hist_kernel<<<ge, 256, 0, sB>>>(vidx, eidx, p_cnt, N_X, E);               // 4
    offsets_kernel<<<nbx + nbw, 1024, 0, sB>>>(p_cnt, p_beg, p_cur, p_ctr,    // 5
                                               N_X, N_W, nbx);
    cudaEventRecord(eOff, sB);
    place_x_kernel<<<ge, 256, 0, sB>>>(vidx, eidx, p_cur, p_srcx, E);         // 6

    // ---- stream C: place_w (overlaps place_x/sr1), then we GEMM ----
    cudaStreamWaitEvent(sC, eOff, 0);
    place_w_kernel<<<ge, 256, 0, sC>>>(vidx, eidx, p_cur, p_srcw,             // 7
                                       p_ctr, N_X, E);
    cudaEventRecord(ePW, sC);
    gemm_hmma_kernel<<<gw, 256, SM_TOT, sC>>>(w, 2, bw2, p_we, N_W,           // 8
                                              nullptr, nullptr, nullptr);
    cudaEventRecord(eC, sC);

    // ---- sr1 on stream B: out_x = xv*(1 + segsum_v(wv)) ----
    cudaStreamWaitEvent(sB, eA, 0);
    cudaStreamWaitEvent(sB, eWV, 0);
    seg_reduce_kernel<<<(N_X + 7) / 8, 256, 0, sB>>>(p_beg, p_cur, p_srcx,    // 9
                                                     p_wv, p_xv, out_x, N_X);

    // ---- sr2 on stream B: s = segsum_e(out_x) ----
    cudaStreamWaitEvent(sB, ePW, 0);
    seg_reduce_kernel<<<(N_W + 7) / 8, 256, 0, sB>>>(p_beg + N_X, p_cur + N_X,// 10
                                                     p_srcw, out_x, nullptr,
                                                     p_s, N_W);

    // ---- final on stream B: w_new = we*(1 + s@Wx2^T + deg_w*bx2) ----
    cudaStreamWaitEvent(sB, eC, 0);
    gemm_hmma_kernel<<<gw, 256, SM_TOT, sB>>>(p_s, 3, bx2, out_w, N_W,        // 11
                                              p_beg + N_X, p_cur + N_X, p_we);

    // join stream B back to the capture (legacy) stream
    cudaEventRecord(eEnd, sB);
    cudaStreamWaitEvent(0, eEnd, 0);
}